// round 4
// baseline (speedup 1.0000x reference)
#include <cuda_runtime.h>
#include <cuda_bf16.h>
#include <cstdint>

// Problem constants: B=32, N=8192, C=512, K=128
#define PB   32
#define PN   8192
#define PC   512
#define PK   128
#define SEGS 8        // CTAs per batch
#define TPB  256      // threads per CTA
#define EPT  4        // elements per thread  (SEGS*TPB*EPT = PN)

// Scratch (zero-init at module load; kernel restores zeros every launch).
// g_stage is fully overwritten each launch (exactly PK writes per batch).
__device__ int          g_stage[PB * PK];
__device__ unsigned int g_cnt[PB];
__device__ unsigned int g_done[PB];

__global__ void __launch_bounds__(TPB) fused_filter_kernel(
    const float* __restrict__ one_hot,
    const int*   __restrict__ id_ptr,
    float*       __restrict__ out)
{
    const int g   = blockIdx.x;          // 0 .. PB*SEGS-1
    const int b   = g >> 3;              // batch
    const int seg = g & (SEGS - 1);      // segment within batch
    const int t   = threadIdx.x;

    const int id = __ldg(id_ptr);
    const int nbase = seg * (TPB * EPT) + t;   // + i*TPB for i in [0,EPT)

    const float* src = one_hot + (size_t)b * PN * PC + id;

    // ---- 4 independent scattered loads (MLP=4, front-batched) ----
    float v[EPT];
#pragma unroll
    for (int i = 0; i < EPT; i++)
        v[i] = __ldg(src + (size_t)(nbase + i * TPB) * PC);

    // ---- block_id output (coalesced) ----
    float* ob = out + (size_t)b * PN;
#pragma unroll
    for (int i = 0; i < EPT; i++)
        ob[nbase + i * TPB] = v[i];

    // ---- stage hit positions (unordered; order fixed by the sorter) ----
#pragma unroll
    for (int i = 0; i < EPT; i++) {
        if (v[i] != 0.0f) {
            unsigned slot = atomicAdd(&g_cnt[b], 1u);
            if (slot < PK) g_stage[b * PK + slot] = nbase + i * TPB;
        }
    }

    // ---- release: make this CTA's stage writes visible, then arrive ----
    __threadfence();
    __syncthreads();

    __shared__ unsigned s_done;
    if (t == 0) s_done = atomicAdd(&g_done[b], 1u);
    __syncthreads();

    if (s_done != SEGS - 1) return;      // not the last CTA of this batch

    // =========== finisher CTA for batch b: rank-sort the 128 hits ==========
    __threadfence();                      // acquire after observing all arrivals

    __shared__ int s_vals[PK];
    if (t < PK) {
        // volatile: bypass any stale caching; data written by other SMs via L2
        s_vals[t] = ((volatile int*)g_stage)[b * PK + t];
    }
    __syncthreads();

    if (t < PK) {
        const int myv = s_vals[t];
        int rank = 0;
#pragma unroll 8
        for (int j = 0; j < PK; j++)
            rank += (s_vals[j] < myv);
        out[(size_t)PB * PN + (size_t)b * PK + rank] = (float)myv;
    }

    // ---- reset scratch for the next graph replay ----
    if (t == 0) {
        g_cnt[b]  = 0u;
        __threadfence();
        atomicExch(&g_done[b], 0u);
    }
}

extern "C" void kernel_launch(void* const* d_in, const int* in_sizes, int n_in,
                              void* d_out, int out_size)
{
    const float* one_hot = (const float*)d_in[0];
    const int*   id_ptr  = (const int*)d_in[1];
    float*       out     = (float*)d_out;

    (void)in_sizes; (void)n_in; (void)out_size;

    fused_filter_kernel<<<PB * SEGS, TPB>>>(one_hot, id_ptr, out);
}